// round 12
// baseline (speedup 1.0000x reference)
#include <cuda_runtime.h>
#include <cuda_bf16.h>
#include <mma.h>
#include <math_constants.h>

using namespace nvcuda;

#define N 512
#define D 64
#define MAX_STEPS 10

// ---- persistent scratch ----
__device__ float         g_p0[N];
__device__ unsigned int  g_cand[MAX_STEPS][N];  // per-step candidate maxima (float bits)
__device__ float         g_rowconst[N * D];     // nf[i]@W1[0:64] + b1
// Bt in tile-major interleaved layout: [jtile][k2][lane*2 + (k&1)]
__device__ __align__(16) float g_Bt2[16][D * 32];
__device__ float         g_f0[N];
__device__ __align__(16) __nv_bfloat16 g_w2hi[D * 32];  // [k][m] = bf16(W2[k][m])
__device__ __align__(16) __nv_bfloat16 g_w2lo[D * 32];  // exact residual

// ---------------------------------------------------------------------------
__global__ void k_init_state(const int* __restrict__ shock, int n_shock) {
    int t = threadIdx.x;                    // 512 threads
    if (t < N) g_p0[t] = 0.f;
    unsigned int* c = &g_cand[0][0];
    for (int idx = t; idx < MAX_STEPS * N; idx += 512) c[idx] = 0u;
    __syncthreads();
    if (t < n_shock) g_p0[shock[t]] = 1.f;
}

__global__ void k_init_ab(const float* __restrict__ nf,
                          const float* __restrict__ W1,
                          const float* __restrict__ b1,
                          const float* __restrict__ W2) {
    int gid = blockIdx.x * 256 + threadIdx.x;      // < 32768
    int i = gid >> 6, k = gid & 63;
    float accA = b1[k];
#pragma unroll 8
    for (int d = 0; d < D; d++) accA = fmaf(nf[i * D + d], W1[d * D + k], accA);
    g_rowconst[gid] = accA;

    int j = gid & (N - 1), kk = gid >> 9;          // kk < 64
    float accB = 0.f;
#pragma unroll 8
    for (int d = 0; d < D; d++) accB = fmaf(nf[j * D + d], W1[(D + d) * D + kk], accB);
    g_Bt2[j >> 5][(kk >> 1) * 64 + (j & 31) * 2 + (kk & 1)] = accB;

    if (gid < N) g_f0[gid] = nf[gid * D];
    if (gid < D * 32) {                            // W2 split, same [k][m] layout as W2
        float w = W2[gid];
        __nv_bfloat16 h = __float2bfloat16(w);
        g_w2hi[gid] = h;
        g_w2lo[gid] = __float2bfloat16(w - __bfloat162float(h));
    }
}

// ---------------------------------------------------------------------------
// Step kernel: block = 64 threads = 2 warps; warp w handles edge row i0+w over
// 32 j-lanes (lane = edge). Layer 2 via wmma bf16 4-pass exact-split, fp32 acc.
#define A_LDM 72          // bf16 elems per A row (144 B: conflict-free, 16B-aligned)
#define D_LDM 36          // f32 elems per D row (144 B)

__global__ void __launch_bounds__(64, 5)
k_edges(const float* __restrict__ cgm, const float* __restrict__ W1,
        const float* __restrict__ b2,  const float* __restrict__ W3,
        const float* __restrict__ b3,  int step, float sf) {
    __shared__ __align__(32) __nv_bfloat16 s_a[2][2][32 * A_LDM]; // [warp][hi/lo]
    __shared__ __align__(32) __nv_bfloat16 s_b[2][D * 32];        // [hi/lo][k][m]
    __shared__ __align__(32) float s_d[2][32 * D_LDM];            // [warp] wmma D out
    __shared__ __align__(16) float s_bt2[D * 32];  // interleaved k-pairs (tile blob)
    __shared__ __align__(16) float s_wq[2 * D];    // (w128,w131) interleaved
    __shared__ float s_rv[2 * D];
    __shared__ float s_w3[32], s_b2[32], s_f0j[32], s_f0i[2], s_pi[2];
    __shared__ unsigned int s_cand[32];
    __shared__ float s_b3;
    __shared__ int s_alive;

    int tid = threadIdx.x;
    int warp = tid >> 5, lane = tid & 31;
    int j0 = blockIdx.x * 32;
    int i0 = blockIdx.y * 2;

    if (tid == 0) s_alive = 0;
    __syncthreads();
    if (tid < 2) {
        float p = g_p0[i0 + tid];                  // replay: p_s = max(p0, cand_0..s-1)
        for (int s = 0; s < step; s++)
            p = fmaxf(p, __uint_as_float(g_cand[s][i0 + tid]));
        s_pi[tid] = p;
        s_f0i[tid] = g_f0[i0 + tid];
        if (p > 0.f) atomicExch(&s_alive, 1);
    }
    __syncthreads();
    if (!s_alive) return;                          // both rows dead (block-uniform)

    {   // tile loads — fully vectorized
        const uint4* w2h4 = (const uint4*)g_w2hi;  // 256 uint4 each
        const uint4* w2l4 = (const uint4*)g_w2lo;
        uint4* sb0 = (uint4*)&s_b[0][0];
        uint4* sb1 = (uint4*)&s_b[1][0];
#pragma unroll
        for (int q = 0; q < 4; q++) {
            sb0[tid + 64 * q] = w2h4[tid + 64 * q];
            sb1[tid + 64 * q] = w2l4[tid + 64 * q];
        }
        const float4* bt4 = (const float4*)&g_Bt2[blockIdx.x][0]; // 512 float4
        float4* sbt4 = (float4*)s_bt2;
#pragma unroll
        for (int q = 0; q < 8; q++) sbt4[tid + 64 * q] = bt4[tid + 64 * q];
        for (int idx = tid; idx < 2 * D; idx += 64) {
            int r = idx >> 6, k = idx & 63;
            s_rv[idx] = fmaf(s_pi[r], W1[129 * D + k],
                        fmaf(sf, W1[130 * D + k], g_rowconst[(i0 + r) * D + k]));
        }
        for (int idx = tid; idx < 128; idx += 64)
            s_wq[idx] = W1[(128 + 3 * (idx & 1)) * D + (idx >> 1)];
        if (tid < 32) { s_w3[tid] = W3[tid]; s_b2[tid] = b2[tid];
                        s_f0j[tid] = g_f0[j0 + tid]; s_cand[tid] = 0u; }
        if (tid == 0) s_b3 = b3[0];
    }
    __syncthreads();

    float p_i = s_pi[warp];                        // warp-uniform guard
    if (p_i > 0.f) {
        float cg = cgm[(i0 + warp) * N + j0 + lane];
        float fd = fabsf(s_f0i[warp] - s_f0j[lane]);

        // ---- layer 1 + exact bf16 split ----
        unsigned ahi[32], alo[32];
        const float2* rv2 = (const float2*)(&s_rv[warp * D]);
        const float2* bt2 = (const float2*)s_bt2;
        const float4* wq4 = (const float4*)s_wq;
#pragma unroll
        for (int k2 = 0; k2 < 32; k2++) {
            float4 wq = wq4[k2];
            float2 rv = rv2[k2];
            float2 bt = bt2[(k2 << 5) + lane];
            float h0 = fmaxf(fmaf(cg, wq.x, fmaf(fd, wq.y, rv.x + bt.x)), 0.f);
            float h1 = fmaxf(fmaf(cg, wq.z, fmaf(fd, wq.w, rv.y + bt.y)), 0.f);
            unsigned hb;
            asm("cvt.rn.bf16x2.f32 %0, %1, %2;" : "=r"(hb) : "f"(h1), "f"(h0));
            float f_lo = __uint_as_float(hb << 16);
            float f_hi = __uint_as_float(hb & 0xFFFF0000u);
            float r0 = h0 - f_lo, r1 = h1 - f_hi;
            unsigned lb;
            asm("cvt.rn.bf16x2.f32 %0, %1, %2;" : "=r"(lb) : "f"(r1), "f"(r0));
            ahi[k2] = hb; alo[k2] = lb;
        }
        // store A rows (lane = edge row), 8x STS.128 each, conflict-free (A_LDM=72)
        uint4* rowh = (uint4*)&s_a[warp][0][lane * A_LDM];
        uint4* rowl = (uint4*)&s_a[warp][1][lane * A_LDM];
#pragma unroll
        for (int q = 0; q < 8; q++) {
            rowh[q] = make_uint4(ahi[4 * q], ahi[4 * q + 1], ahi[4 * q + 2], ahi[4 * q + 3]);
            rowl[q] = make_uint4(alo[4 * q], alo[4 * q + 1], alo[4 * q + 2], alo[4 * q + 3]);
        }
        __syncwarp();

        // ---- layer 2: wmma, 4 passes (exact product of 2-term splits) ----
        wmma::fragment<wmma::accumulator, 16, 16, 16, float> acc[2][2];
#pragma unroll
        for (int r = 0; r < 2; r++)
#pragma unroll
            for (int c = 0; c < 2; c++) wmma::fill_fragment(acc[r][c], 0.f);

#pragma unroll
        for (int ks = 0; ks < 4; ks++) {
            wmma::fragment<wmma::matrix_a, 16, 16, 16, __nv_bfloat16, wmma::row_major> a_hi[2], a_lo[2];
            wmma::fragment<wmma::matrix_b, 16, 16, 16, __nv_bfloat16, wmma::row_major> b_hi[2], b_lo[2];
#pragma unroll
            for (int r = 0; r < 2; r++) {
                wmma::load_matrix_sync(a_hi[r], &s_a[warp][0][r * 16 * A_LDM + ks * 16], A_LDM);
                wmma::load_matrix_sync(a_lo[r], &s_a[warp][1][r * 16 * A_LDM + ks * 16], A_LDM);
            }
#pragma unroll
            for (int c = 0; c < 2; c++) {
                wmma::load_matrix_sync(b_hi[c], &s_b[0][ks * 16 * 32 + c * 16], 32);
                wmma::load_matrix_sync(b_lo[c], &s_b[1][ks * 16 * 32 + c * 16], 32);
            }
#pragma unroll
            for (int r = 0; r < 2; r++)
#pragma unroll
                for (int c = 0; c < 2; c++) {
                    wmma::mma_sync(acc[r][c], a_hi[r], b_hi[c], acc[r][c]);
                    wmma::mma_sync(acc[r][c], a_lo[r], b_hi[c], acc[r][c]);
                    wmma::mma_sync(acc[r][c], a_hi[r], b_lo[c], acc[r][c]);
                    wmma::mma_sync(acc[r][c], a_lo[r], b_lo[c], acc[r][c]);
                }
        }

        // ---- write D to dedicated buffer ----
#pragma unroll
        for (int r = 0; r < 2; r++)
#pragma unroll
            for (int c = 0; c < 2; c++)
                wmma::store_matrix_sync(&s_d[warp][r * 16 * D_LDM + c * 16], acc[r][c],
                                        D_LDM, wmma::mem_row_major);
        __syncwarp();

        // ---- epilogue: lane reads its edge row ----
        const float* drow = &s_d[warp][lane * D_LDM];
        float z = s_b3;
#pragma unroll
        for (int m = 0; m < 32; m++)
            z = fmaf(fmaxf(drow[m] + s_b2[m], 0.f), s_w3[m], z);
        float tr = 1.f / (1.f + __expf(-z));
        float val = (cg > 0.f) ? p_i * tr * cg : 0.f;
        if (val > 0.f) atomicMax(&s_cand[lane], __float_as_uint(val)); // >=0: uint==float order
    }
    __syncthreads();
    if (tid < 32) {
        unsigned v = s_cand[tid];
        if (v) atomicMax(&g_cand[step][j0 + tid], v);
    }
}

// replay the 10-step max/arr recurrence exactly; write output
__global__ void k_final(float* __restrict__ out) {
    int j = threadIdx.x;                            // 512 threads
    float p = g_p0[j];
    float arr = (p > 0.f) ? 0.f : CUDART_INF_F;
#pragma unroll
    for (int s = 0; s < MAX_STEPS; s++) {
        float c = __uint_as_float(g_cand[s][j]);
        if (c > p) { p = c; arr = fminf(arr, (float)(s + 1)); }
    }
    out[j] = p; out[N + j] = arr;
}

// ---------------------------------------------------------------------------
extern "C" void kernel_launch(void* const* d_in, const int* in_sizes, int n_in,
                              void* d_out, int out_size) {
    const float* cg    = (const float*)d_in[0];
    const float* nf    = (const float*)d_in[1];
    const int*   shock = (const int*)  d_in[2];
    const float* W1    = (const float*)d_in[3];
    const float* b1    = (const float*)d_in[4];
    const float* W2    = (const float*)d_in[5];
    const float* b2    = (const float*)d_in[6];
    const float* W3    = (const float*)d_in[7];
    const float* b3    = (const float*)d_in[8];
    float* out = (float*)d_out;

    k_init_state<<<1, 512>>>(shock, in_sizes[2]);
    k_init_ab<<<128, 256>>>(nf, W1, b1, W2);
    for (int s = 0; s < MAX_STEPS; s++)
        k_edges<<<dim3(16, 256), 64>>>(cg, W1, b2, W3, b3,
                                       s, (float)s / (float)MAX_STEPS);
    k_final<<<1, 512>>>(out);
}

// round 13
// speedup vs baseline: 1.3228x; 1.3228x over previous
#include <cuda_runtime.h>
#include <cuda_bf16.h>
#include <mma.h>
#include <math_constants.h>

using namespace nvcuda;

#define N 512
#define D 64
#define MAX_STEPS 10

// ---- persistent scratch ----
__device__ float         g_p0[N];
__device__ unsigned int  g_cand[MAX_STEPS][N];  // per-step candidate maxima (float bits)
__device__ float         g_rowconst[N * D];     // nf[i]@W1[0:64] + b1
// Bt in tile-major interleaved layout: [jtile][k2*64 + lane*2 + (k&1)]
__device__ __align__(16) float g_Bt2[16][D * 32];
__device__ float         g_f0[N];
__device__ __align__(16) __nv_bfloat16 g_w2hi[D * 32];  // [k][m] = bf16(W2[k][m])
__device__ __align__(16) __nv_bfloat16 g_w2lo[D * 32];  // exact residual

// ---------------------------------------------------------------------------
__global__ void k_init_state(const int* __restrict__ shock, int n_shock) {
    int t = threadIdx.x;                    // 512 threads
    if (t < N) g_p0[t] = 0.f;
    unsigned int* c = &g_cand[0][0];
    for (int idx = t; idx < MAX_STEPS * N; idx += 512) c[idx] = 0u;
    __syncthreads();
    if (t < n_shock) g_p0[shock[t]] = 1.f;
}

__global__ void k_init_ab(const float* __restrict__ nf,
                          const float* __restrict__ W1,
                          const float* __restrict__ b1,
                          const float* __restrict__ W2) {
    int gid = blockIdx.x * 256 + threadIdx.x;      // < 32768
    int i = gid >> 6, k = gid & 63;
    float accA = b1[k];
#pragma unroll 8
    for (int d = 0; d < D; d++) accA = fmaf(nf[i * D + d], W1[d * D + k], accA);
    g_rowconst[gid] = accA;

    int j = gid & (N - 1), kk = gid >> 9;          // kk < 64
    float accB = 0.f;
#pragma unroll 8
    for (int d = 0; d < D; d++) accB = fmaf(nf[j * D + d], W1[(D + d) * D + kk], accB);
    g_Bt2[j >> 5][(kk >> 1) * 64 + (j & 31) * 2 + (kk & 1)] = accB;

    if (gid < N) g_f0[gid] = nf[gid * D];
    if (gid < D * 32) {                            // W2 split, same [k][m] layout as W2
        float w = W2[gid];
        __nv_bfloat16 h = __float2bfloat16(w);
        g_w2hi[gid] = h;
        g_w2lo[gid] = __float2bfloat16(w - __bfloat162float(h));
    }
}

// ---------------------------------------------------------------------------
// Step kernel: 128 threads = 4 warps; warp w owns edge row i0+w across 32 j.
// Layer 2: wmma bf16 3-pass split (hi.hi + lo.hi + hi.lo), fp32 accumulate.
// A staged in 16-k chunks (per-warp 3KB buffer recycled); D overlays Bt+A.
#define A_LDM 24          // bf16 elems per chunk row (48 B)
#define D_LDM 36          // f32 elems per D row (144 B)

__global__ void __launch_bounds__(128, 4)
k_edges(const float* __restrict__ cgm, const float* __restrict__ W1,
        const float* __restrict__ b2,  const float* __restrict__ W3,
        const float* __restrict__ b3,  int step, float sf) {
    __shared__ __align__(32) unsigned char pool[30976];
    // layout (bytes):
    //   [0,4096)        s_bh : W2 hi [k][m]
    //   [4096,8192)     s_bl : W2 lo
    //   [8192,16384)    s_bt2: Bt interleaved tile      } overlaid by s_d
    //   [16384,28672)   s_a  : 4 warps x (hi1536+lo1536)} (18432 B from 8192)
    //   [28672,29696)   s_rv : 4 x 64
    //   [29696,30208)   s_wq : (w128,w131) interleaved
    //   [30208,30336)   s_w3 ; [30336,30464) s_b2 ; [30464,30592) s_f0j
    //   [30592..] s_f0i[4], s_pi[4], s_cand[32], s_b3, s_alive
    __nv_bfloat16* s_bh = (__nv_bfloat16*)(pool);
    __nv_bfloat16* s_bl = (__nv_bfloat16*)(pool + 4096);
    float* s_bt2 = (float*)(pool + 8192);
    __nv_bfloat16* s_a = (__nv_bfloat16*)(pool + 16384);
    float* s_dov = (float*)(pool + 8192);          // D overlay (post-sync)
    float* s_rv = (float*)(pool + 28672);
    float* s_wq = (float*)(pool + 29696);
    float* s_w3 = (float*)(pool + 30208);
    float* s_b2 = (float*)(pool + 30336);
    float* s_f0j = (float*)(pool + 30464);
    float* s_f0i = (float*)(pool + 30592);
    float* s_pi  = (float*)(pool + 30608);
    unsigned* s_cand = (unsigned*)(pool + 30624);
    float* s_b3p = (float*)(pool + 30752);
    int* s_alive = (int*)(pool + 30756);

    int tid = threadIdx.x;
    int warp = tid >> 5, lane = tid & 31;
    int j0 = blockIdx.x * 32;
    int i0 = blockIdx.y * 4;

    if (tid == 0) *s_alive = 0;
    __syncthreads();
    if (tid < 4) {
        float p = g_p0[i0 + tid];                  // replay: p_s = max(p0, cand_0..s-1)
        for (int s = 0; s < step; s++)
            p = fmaxf(p, __uint_as_float(g_cand[s][i0 + tid]));
        s_pi[tid] = p;
        s_f0i[tid] = g_f0[i0 + tid];
        if (p > 0.f) atomicExch(s_alive, 1);
    }
    __syncthreads();
    if (!*s_alive) return;                         // all 4 rows dead (block-uniform)

    {   // prologue — vectorized
        const uint4* w2h4 = (const uint4*)g_w2hi;  // 256 uint4 each
        const uint4* w2l4 = (const uint4*)g_w2lo;
        uint4* sb0 = (uint4*)s_bh;
        uint4* sb1 = (uint4*)s_bl;
#pragma unroll
        for (int q = 0; q < 2; q++) {
            sb0[tid + 128 * q] = w2h4[tid + 128 * q];
            sb1[tid + 128 * q] = w2l4[tid + 128 * q];
        }
        const float4* bt4 = (const float4*)&g_Bt2[blockIdx.x][0]; // 512 float4
        float4* sbt4 = (float4*)s_bt2;
#pragma unroll
        for (int q = 0; q < 4; q++) sbt4[tid + 128 * q] = bt4[tid + 128 * q];
        for (int idx = tid; idx < 4 * D; idx += 128) {
            int r = idx >> 6, k = idx & 63;
            s_rv[idx] = fmaf(s_pi[r], W1[129 * D + k],
                        fmaf(sf, W1[130 * D + k], g_rowconst[(i0 + r) * D + k]));
        }
        if (tid < 128) s_wq[tid] = W1[(128 + 3 * (tid & 1)) * D + (tid >> 1)];
        if (tid < 32) { s_w3[tid] = W3[tid]; s_b2[tid] = b2[tid];
                        s_f0j[tid] = g_f0[j0 + tid]; s_cand[tid] = 0u; }
        if (tid == 0) *s_b3p = b3[0];
    }
    __syncthreads();

    float p_i = s_pi[warp];                        // warp-uniform guard
    float cg = 0.f;
    wmma::fragment<wmma::accumulator, 16, 16, 16, float> acc[2][2];

    if (p_i > 0.f) {
        cg = cgm[(i0 + warp) * N + j0 + lane];
        float fd = fabsf(s_f0i[warp] - s_f0j[lane]);
#pragma unroll
        for (int r = 0; r < 2; r++)
#pragma unroll
            for (int c = 0; c < 2; c++) wmma::fill_fragment(acc[r][c], 0.f);

        __nv_bfloat16* a_hi = s_a + warp * 1536;   // 32 rows x A_LDM
        __nv_bfloat16* a_lo = a_hi + 768;          // (1536 elems = 3072 B per warp)
        const float2* rv2 = (const float2*)(s_rv + warp * D);
        const float2* bt2 = (const float2*)s_bt2;
        const float4* wq4 = (const float4*)s_wq;

#pragma unroll
        for (int ks = 0; ks < 4; ks++) {
            // ---- layer 1 for this 16-k chunk + exact bf16 split ----
            unsigned ahi[4], alo[4];
#pragma unroll
            for (int q = 0; q < 8; q++) {
                int k2 = ks * 8 + q;
                float4 wq = wq4[k2];
                float2 rv = rv2[k2];
                float2 bt = bt2[(k2 << 5) + lane];
                float h0 = fmaxf(fmaf(cg, wq.x, fmaf(fd, wq.y, rv.x + bt.x)), 0.f);
                float h1 = fmaxf(fmaf(cg, wq.z, fmaf(fd, wq.w, rv.y + bt.y)), 0.f);
                unsigned hb;
                asm("cvt.rn.bf16x2.f32 %0, %1, %2;" : "=r"(hb) : "f"(h1), "f"(h0));
                float f_lo = __uint_as_float(hb << 16);
                float f_hi = __uint_as_float(hb & 0xFFFF0000u);
                float r0 = h0 - f_lo, r1 = h1 - f_hi;
                unsigned lb;
                asm("cvt.rn.bf16x2.f32 %0, %1, %2;" : "=r"(lb) : "f"(r1), "f"(r0));
                ahi[q & 3] = hb; alo[q & 3] = lb;
                if ((q & 3) == 3) {                // flush 8 k's = 16 B per buffer
                    int half = q >> 2;             // 0 or 1
                    *(uint4*)((char*)a_hi + lane * 48 + half * 16) =
                        make_uint4(ahi[0], ahi[1], ahi[2], ahi[3]);
                    *(uint4*)((char*)a_lo + lane * 24 * 2 + half * 16) =
                        make_uint4(alo[0], alo[1], alo[2], alo[3]);
                }
            }
            __syncwarp();

            // ---- fragments + 3-pass mma ----
            wmma::fragment<wmma::matrix_a, 16, 16, 16, __nv_bfloat16, wmma::row_major> fa_hi[2], fa_lo[2];
            wmma::fragment<wmma::matrix_b, 16, 16, 16, __nv_bfloat16, wmma::row_major> fb_hi[2], fb_lo[2];
#pragma unroll
            for (int r = 0; r < 2; r++) {
                wmma::load_matrix_sync(fa_hi[r], a_hi + r * 16 * A_LDM, A_LDM);
                wmma::load_matrix_sync(fa_lo[r], a_lo + r * 16 * A_LDM, A_LDM);
            }
#pragma unroll
            for (int c = 0; c < 2; c++) {
                wmma::load_matrix_sync(fb_hi[c], s_bh + ks * 16 * 32 + c * 16, 32);
                wmma::load_matrix_sync(fb_lo[c], s_bl + ks * 16 * 32 + c * 16, 32);
            }
#pragma unroll
            for (int r = 0; r < 2; r++)
#pragma unroll
                for (int c = 0; c < 2; c++) {
                    wmma::mma_sync(acc[r][c], fa_hi[r], fb_hi[c], acc[r][c]);
                    wmma::mma_sync(acc[r][c], fa_lo[r], fb_hi[c], acc[r][c]);
                    wmma::mma_sync(acc[r][c], fa_hi[r], fb_lo[c], acc[r][c]);
                }
        }
    }
    __syncthreads();                               // Bt + A dead; D overlay now safe

    if (p_i > 0.f) {
        float* dw = s_dov + warp * (32 * D_LDM);
#pragma unroll
        for (int r = 0; r < 2; r++)
#pragma unroll
            for (int c = 0; c < 2; c++)
                wmma::store_matrix_sync(dw + r * 16 * D_LDM + c * 16, acc[r][c],
                                        D_LDM, wmma::mem_row_major);
        __syncwarp();

        const float* drow = dw + lane * D_LDM;     // lane's edge row
        float z = *s_b3p;
#pragma unroll
        for (int m = 0; m < 32; m++)
            z = fmaf(fmaxf(drow[m] + s_b2[m], 0.f), s_w3[m], z);
        float tr = 1.f / (1.f + __expf(-z));
        float val = (cg > 0.f) ? p_i * tr * cg : 0.f;
        if (val > 0.f) atomicMax(&s_cand[lane], __float_as_uint(val)); // uint==float order for >=0
    }
    __syncthreads();
    if (tid < 32) {
        unsigned v = s_cand[tid];
        if (v) atomicMax(&g_cand[step][j0 + tid], v);
    }
}

// replay the 10-step max/arr recurrence exactly; write output
__global__ void k_final(float* __restrict__ out) {
    int j = threadIdx.x;                            // 512 threads
    float p = g_p0[j];
    float arr = (p > 0.f) ? 0.f : CUDART_INF_F;
#pragma unroll
    for (int s = 0; s < MAX_STEPS; s++) {
        float c = __uint_as_float(g_cand[s][j]);
        if (c > p) { p = c; arr = fminf(arr, (float)(s + 1)); }
    }
    out[j] = p; out[N + j] = arr;
}

// ---------------------------------------------------------------------------
extern "C" void kernel_launch(void* const* d_in, const int* in_sizes, int n_in,
                              void* d_out, int out_size) {
    const float* cg    = (const float*)d_in[0];
    const float* nf    = (const float*)d_in[1];
    const int*   shock = (const int*)  d_in[2];
    const float* W1    = (const float*)d_in[3];
    const float* b1    = (const float*)d_in[4];
    const float* W2    = (const float*)d_in[5];
    const float* b2    = (const float*)d_in[6];
    const float* W3    = (const float*)d_in[7];
    const float* b3    = (const float*)d_in[8];
    float* out = (float*)d_out;

    k_init_state<<<1, 512>>>(shock, in_sizes[2]);
    k_init_ab<<<128, 256>>>(nf, W1, b1, W2);
    for (int s = 0; s < MAX_STEPS; s++)
        k_edges<<<dim3(16, 128), 128>>>(cg, W1, b2, W3, b3,
                                        s, (float)s / (float)MAX_STEPS);
    k_final<<<1, 512>>>(out);
}

// round 14
// speedup vs baseline: 1.4307x; 1.0815x over previous
#include <cuda_runtime.h>
#include <cuda_bf16.h>
#include <mma.h>
#include <math_constants.h>

using namespace nvcuda;

#define N 512
#define D 64
#define MAX_STEPS 10
#define B_LDM 40          // bf16 elems per W2 smem row (80 B: conflict-free ldmatrix)
#define A_LDM 24          // bf16 elems per A chunk row (48 B)
#define D_LDM 36          // f32 elems per D row (144 B); reads rotated -> conflict-free

// ---- persistent scratch ----
__device__ float         g_p0[N];
__device__ unsigned int  g_cand[MAX_STEPS][N];  // per-step candidate maxima (float bits)
__device__ float         g_rowconst[N * D];     // nf[i]@W1[0:64] + b1
// Bt in tile-major interleaved layout: [jtile][k2*64 + lane*2 + (k&1)]
__device__ __align__(16) float g_Bt2[16][D * 32];
__device__ float         g_f0[N];
__device__ __align__(16) __nv_bfloat16 g_w2hi[D * B_LDM];  // padded [k][B_LDM]
__device__ __align__(16) __nv_bfloat16 g_w2lo[D * B_LDM];  // exact residual, padded

// ---------------------------------------------------------------------------
__global__ void k_init_state(const int* __restrict__ shock, int n_shock) {
    int t = threadIdx.x;                    // 512 threads
    if (t < N) g_p0[t] = 0.f;
    unsigned int* c = &g_cand[0][0];
    for (int idx = t; idx < MAX_STEPS * N; idx += 512) c[idx] = 0u;
    __syncthreads();
    if (t < n_shock) g_p0[shock[t]] = 1.f;
}

__global__ void k_init_ab(const float* __restrict__ nf,
                          const float* __restrict__ W1,
                          const float* __restrict__ b1,
                          const float* __restrict__ W2) {
    int gid = blockIdx.x * 256 + threadIdx.x;      // < 32768
    int i = gid >> 6, k = gid & 63;
    float accA = b1[k];
#pragma unroll 8
    for (int d = 0; d < D; d++) accA = fmaf(nf[i * D + d], W1[d * D + k], accA);
    g_rowconst[gid] = accA;

    int j = gid & (N - 1), kk = gid >> 9;          // kk < 64
    float accB = 0.f;
#pragma unroll 8
    for (int d = 0; d < D; d++) accB = fmaf(nf[j * D + d], W1[(D + d) * D + kk], accB);
    g_Bt2[j >> 5][(kk >> 1) * 64 + (j & 31) * 2 + (kk & 1)] = accB;

    if (gid < N) g_f0[gid] = nf[gid * D];
    if (gid < D * 32) {                            // W2 split into padded [k][B_LDM]
        int kw = gid >> 5, m = gid & 31;
        float w = W2[gid];                         // W2 is [k][m] row-major, m=32
        __nv_bfloat16 h = __float2bfloat16(w);
        g_w2hi[kw * B_LDM + m] = h;
        g_w2lo[kw * B_LDM + m] = __float2bfloat16(w - __bfloat162float(h));
    }
}

// ---------------------------------------------------------------------------
// Step kernel: 128 threads = 4 warps; warp w owns edge row i0+w across 32 j.
// Layer 2: wmma bf16 3-pass split (hi.hi + lo.hi + hi.lo), fp32 accumulate.
__global__ void __launch_bounds__(128, 4)
k_edges(const float* __restrict__ cgm, const float* __restrict__ W1,
        const float* __restrict__ b2,  const float* __restrict__ W3,
        const float* __restrict__ b3,  int step, float sf) {
    __shared__ __align__(32) unsigned char pool[33536];
    // layout (bytes):
    //   [0,5120)        s_bh : W2 hi [k][B_LDM]
    //   [5120,10240)    s_bl : W2 lo
    //   [10240,18432)   s_bt2: Bt interleaved tile   } overlaid by s_dov
    //   [18432,30720)   s_a  : 4 warps x 3072        } (18432 B from 10240)
    //   [30720,31744)   s_rv ; [31744,32256) s_wq
    //   [32256,32512)   s_bw : (b2,w3) float2 pairs
    //   [32512,32640)   s_f0j; then f0i[4], pi[4], cand[32], b3, alive
    __nv_bfloat16* s_bh = (__nv_bfloat16*)(pool);
    __nv_bfloat16* s_bl = (__nv_bfloat16*)(pool + 5120);
    float* s_bt2 = (float*)(pool + 10240);
    __nv_bfloat16* s_a = (__nv_bfloat16*)(pool + 18432);
    float* s_dov = (float*)(pool + 10240);         // D overlay (post-sync), 18432 B
    float* s_rv = (float*)(pool + 30720);
    float* s_wq = (float*)(pool + 31744);
    float2* s_bw = (float2*)(pool + 32256);
    float* s_f0j = (float*)(pool + 32512);
    float* s_f0i = (float*)(pool + 32640);
    float* s_pi  = (float*)(pool + 32656);
    unsigned* s_cand = (unsigned*)(pool + 32672);
    float* s_b3p = (float*)(pool + 32800);
    int* s_alive = (int*)(pool + 32804);

    int tid = threadIdx.x;
    int warp = tid >> 5, lane = tid & 31;
    int j0 = blockIdx.x * 32;
    int i0 = blockIdx.y * 4;

    if (tid == 0) *s_alive = 0;
    __syncthreads();
    if (tid < 4) {
        float p = g_p0[i0 + tid];                  // replay: p_s = max(p0, cand_0..s-1)
        for (int s = 0; s < step; s++)
            p = fmaxf(p, __uint_as_float(g_cand[s][i0 + tid]));
        s_pi[tid] = p;
        s_f0i[tid] = g_f0[i0 + tid];
        if (p > 0.f) atomicExch(s_alive, 1);
    }
    __syncthreads();
    if (!*s_alive) return;                         // all 4 rows dead (block-uniform)

    {   // prologue — vectorized
        const uint4* w2h4 = (const uint4*)g_w2hi;  // 320 uint4 each
        const uint4* w2l4 = (const uint4*)g_w2lo;
        uint4* sb0 = (uint4*)s_bh;
        uint4* sb1 = (uint4*)s_bl;
        for (int idx = tid; idx < 320; idx += 128) {
            sb0[idx] = w2h4[idx];
            sb1[idx] = w2l4[idx];
        }
        const float4* bt4 = (const float4*)&g_Bt2[blockIdx.x][0]; // 512 float4
        float4* sbt4 = (float4*)s_bt2;
#pragma unroll
        for (int q = 0; q < 4; q++) sbt4[tid + 128 * q] = bt4[tid + 128 * q];
        for (int idx = tid; idx < 4 * D; idx += 128) {
            int r = idx >> 6, k = idx & 63;
            s_rv[idx] = fmaf(s_pi[r], W1[129 * D + k],
                        fmaf(sf, W1[130 * D + k], g_rowconst[(i0 + r) * D + k]));
        }
        if (tid < 128) s_wq[tid] = W1[(128 + 3 * (tid & 1)) * D + (tid >> 1)];
        if (tid < 32) { s_bw[tid] = make_float2(b2[tid], W3[tid]);
                        s_f0j[tid] = g_f0[j0 + tid]; s_cand[tid] = 0u; }
        if (tid == 0) *s_b3p = b3[0];
    }
    __syncthreads();

    float p_i = s_pi[warp];                        // warp-uniform guard
    float cg = 0.f;
    wmma::fragment<wmma::accumulator, 16, 16, 16, float> acc[2][2];

    if (p_i > 0.f) {
        cg = cgm[(i0 + warp) * N + j0 + lane];
        float fd = fabsf(s_f0i[warp] - s_f0j[lane]);
#pragma unroll
        for (int r = 0; r < 2; r++)
#pragma unroll
            for (int c = 0; c < 2; c++) wmma::fill_fragment(acc[r][c], 0.f);

        __nv_bfloat16* a_hi = s_a + warp * 1536;   // 32 rows x A_LDM
        __nv_bfloat16* a_lo = a_hi + 768;
        const float2* rv2 = (const float2*)(s_rv + warp * D);
        const float2* bt2 = (const float2*)s_bt2;
        const float4* wq4 = (const float4*)s_wq;

#pragma unroll
        for (int ks = 0; ks < 4; ks++) {
            // ---- layer 1 for this 16-k chunk + exact bf16 split ----
            unsigned ahi[4], alo[4];
#pragma unroll
            for (int q = 0; q < 8; q++) {
                int k2 = ks * 8 + q;
                float4 wq = wq4[k2];
                float2 rv = rv2[k2];
                float2 bt = bt2[(k2 << 5) + lane];
                float h0 = fmaxf(fmaf(cg, wq.x, fmaf(fd, wq.y, rv.x + bt.x)), 0.f);
                float h1 = fmaxf(fmaf(cg, wq.z, fmaf(fd, wq.w, rv.y + bt.y)), 0.f);
                unsigned hb;
                asm("cvt.rn.bf16x2.f32 %0, %1, %2;" : "=r"(hb) : "f"(h1), "f"(h0));
                float f_lo = __uint_as_float(hb << 16);
                float f_hi = __uint_as_float(hb & 0xFFFF0000u);
                float r0 = h0 - f_lo, r1 = h1 - f_hi;
                unsigned lb;
                asm("cvt.rn.bf16x2.f32 %0, %1, %2;" : "=r"(lb) : "f"(r1), "f"(r0));
                ahi[q & 3] = hb; alo[q & 3] = lb;
                if ((q & 3) == 3) {                // flush 8 k's = 16 B per buffer
                    int half = q >> 2;             // 0 or 1
                    *(uint4*)((char*)a_hi + lane * 48 + half * 16) =
                        make_uint4(ahi[0], ahi[1], ahi[2], ahi[3]);
                    *(uint4*)((char*)a_lo + lane * 48 + half * 16) =
                        make_uint4(alo[0], alo[1], alo[2], alo[3]);
                }
            }
            __syncwarp();

            // ---- fragments + 3-pass mma ----
            wmma::fragment<wmma::matrix_a, 16, 16, 16, __nv_bfloat16, wmma::row_major> fa_hi[2], fa_lo[2];
            wmma::fragment<wmma::matrix_b, 16, 16, 16, __nv_bfloat16, wmma::row_major> fb_hi[2], fb_lo[2];
#pragma unroll
            for (int r = 0; r < 2; r++) {
                wmma::load_matrix_sync(fa_hi[r], a_hi + r * 16 * A_LDM, A_LDM);
                wmma::load_matrix_sync(fa_lo[r], a_lo + r * 16 * A_LDM, A_LDM);
            }
#pragma unroll
            for (int c = 0; c < 2; c++) {
                wmma::load_matrix_sync(fb_hi[c], s_bh + ks * 16 * B_LDM + c * 16, B_LDM);
                wmma::load_matrix_sync(fb_lo[c], s_bl + ks * 16 * B_LDM + c * 16, B_LDM);
            }
#pragma unroll
            for (int r = 0; r < 2; r++)
#pragma unroll
                for (int c = 0; c < 2; c++) {
                    wmma::mma_sync(acc[r][c], fa_hi[r], fb_hi[c], acc[r][c]);
                    wmma::mma_sync(acc[r][c], fa_lo[r], fb_hi[c], acc[r][c]);
                    wmma::mma_sync(acc[r][c], fa_hi[r], fb_lo[c], acc[r][c]);
                }
        }
    }
    __syncthreads();                               // Bt + A dead; D overlay now safe

    if (p_i > 0.f) {
        float* dw = s_dov + warp * (32 * D_LDM);
#pragma unroll
        for (int r = 0; r < 2; r++)
#pragma unroll
            for (int c = 0; c < 2; c++)
                wmma::store_matrix_sync(dw + r * 16 * D_LDM + c * 16, acc[r][c],
                                        D_LDM, wmma::mem_row_major);
        __syncwarp();

        // epilogue: rotated reads -> bank = (5*lane + m) mod 32, conflict-free
        const float* drow = dw + lane * D_LDM;
        float z = *s_b3p;
#pragma unroll
        for (int m = 0; m < 32; m++) {
            int mm = (lane + m) & 31;
            float2 bw = s_bw[mm];
            z = fmaf(fmaxf(drow[mm] + bw.x, 0.f), bw.y, z);
        }
        float tr = 1.f / (1.f + __expf(-z));
        float val = (cg > 0.f) ? p_i * tr * cg : 0.f;
        if (val > 0.f) atomicMax(&s_cand[lane], __float_as_uint(val)); // uint==float order for >=0
    }
    __syncthreads();
    if (tid < 32) {
        unsigned v = s_cand[tid];
        if (v) atomicMax(&g_cand[step][j0 + tid], v);
    }
}

// replay the 10-step max/arr recurrence exactly; write output
__global__ void k_final(float* __restrict__ out) {
    int j = threadIdx.x;                            // 512 threads
    float p = g_p0[j];
    float arr = (p > 0.f) ? 0.f : CUDART_INF_F;
#pragma unroll
    for (int s = 0; s < MAX_STEPS; s++) {
        float c = __uint_as_float(g_cand[s][j]);
        if (c > p) { p = c; arr = fminf(arr, (float)(s + 1)); }
    }
    out[j] = p; out[N + j] = arr;
}

// ---------------------------------------------------------------------------
extern "C" void kernel_launch(void* const* d_in, const int* in_sizes, int n_in,
                              void* d_out, int out_size) {
    const float* cg    = (const float*)d_in[0];
    const float* nf    = (const float*)d_in[1];
    const int*   shock = (const int*)  d_in[2];
    const float* W1    = (const float*)d_in[3];
    const float* b1    = (const float*)d_in[4];
    const float* W2    = (const float*)d_in[5];
    const float* b2    = (const float*)d_in[6];
    const float* W3    = (const float*)d_in[7];
    const float* b3    = (const float*)d_in[8];
    float* out = (float*)d_out;

    k_init_state<<<1, 512>>>(shock, in_sizes[2]);
    k_init_ab<<<128, 256>>>(nf, W1, b1, W2);
    for (int s = 0; s < MAX_STEPS; s++)
        k_edges<<<dim3(16, 128), 128>>>(cg, W1, b2, W3, b3,
                                        s, (float)s / (float)MAX_STEPS);
    k_final<<<1, 512>>>(out);
}

// round 15
// speedup vs baseline: 1.8315x; 1.2802x over previous
#include <cuda_runtime.h>
#include <cuda_bf16.h>
#include <math_constants.h>

#define N 512
#define D 64
#define MAX_STEPS 10
#define BT_LDM 72         // bf16 per W2^T row (144 B; ldmatrix conflict-free, pad unread)
#define A_LDM 24          // bf16 per A chunk row (48 B; ldmatrix conflict-free)

// ---- persistent scratch ----
__device__ float         g_p0[N];
__device__ unsigned int  g_cand[MAX_STEPS][N];  // per-step candidate maxima (float bits)
__device__ float         g_rowconst[N * D];     // nf[i]@W1[0:64] + b1
// Bt in tile-major interleaved layout: [jtile][k2*64 + lane*2 + (k&1)]
__device__ __align__(16) float g_Bt2[16][D * 32];
__device__ float         g_f0[N];
__device__ __align__(16) __nv_bfloat16 g_w2hiT[32 * BT_LDM]; // [m][k] transposed, padded
__device__ __align__(16) __nv_bfloat16 g_w2loT[32 * BT_LDM]; // exact residual, transposed

// ---- mma / ldmatrix helpers ----
__device__ __forceinline__ unsigned smem_u32(const void* p) {
    return (unsigned)__cvta_generic_to_shared(p);
}
__device__ __forceinline__ void ldm_x4(unsigned& r0, unsigned& r1, unsigned& r2, unsigned& r3,
                                       unsigned addr) {
    asm volatile("ldmatrix.sync.aligned.m8n8.x4.shared.b16 {%0,%1,%2,%3}, [%4];"
                 : "=r"(r0), "=r"(r1), "=r"(r2), "=r"(r3) : "r"(addr));
}
__device__ __forceinline__ void mma_bf16(float* d, const unsigned* a, unsigned b0, unsigned b1) {
    asm volatile("mma.sync.aligned.m16n8k16.row.col.f32.bf16.bf16.f32 "
                 "{%0,%1,%2,%3}, {%4,%5,%6,%7}, {%8,%9}, {%0,%1,%2,%3};"
                 : "+f"(d[0]), "+f"(d[1]), "+f"(d[2]), "+f"(d[3])
                 : "r"(a[0]), "r"(a[1]), "r"(a[2]), "r"(a[3]), "r"(b0), "r"(b1));
}

// ---------------------------------------------------------------------------
__global__ void k_init_state(const int* __restrict__ shock, int n_shock) {
    int t = threadIdx.x;                    // 512 threads
    if (t < N) g_p0[t] = 0.f;
    unsigned int* c = &g_cand[0][0];
    for (int idx = t; idx < MAX_STEPS * N; idx += 512) c[idx] = 0u;
    __syncthreads();
    if (t < n_shock) g_p0[shock[t]] = 1.f;
}

__global__ void k_init_ab(const float* __restrict__ nf,
                          const float* __restrict__ W1,
                          const float* __restrict__ b1,
                          const float* __restrict__ W2) {
    int gid = blockIdx.x * 256 + threadIdx.x;      // < 32768
    int i = gid >> 6, k = gid & 63;
    float accA = b1[k];
#pragma unroll 8
    for (int d = 0; d < D; d++) accA = fmaf(nf[i * D + d], W1[d * D + k], accA);
    g_rowconst[gid] = accA;

    int j = gid & (N - 1), kk = gid >> 9;          // kk < 64
    float accB = 0.f;
#pragma unroll 8
    for (int d = 0; d < D; d++) accB = fmaf(nf[j * D + d], W1[(D + d) * D + kk], accB);
    g_Bt2[j >> 5][(kk >> 1) * 64 + (j & 31) * 2 + (kk & 1)] = accB;

    if (gid < N) g_f0[gid] = nf[gid * D];
    if (gid < D * 32) {                            // W2 split, transposed to [m][k]
        int kw = gid >> 5, m = gid & 31;
        float w = W2[gid];                         // W2 row-major [k][m]
        __nv_bfloat16 h = __float2bfloat16(w);
        g_w2hiT[m * BT_LDM + kw] = h;
        g_w2loT[m * BT_LDM + kw] = __float2bfloat16(w - __bfloat162float(h));
    }
}

// ---------------------------------------------------------------------------
// Step kernel: 128 threads = 4 warps; warp w owns edge row i0+w across 32 j.
// Layer 2: mma.sync m16n8k16 bf16 3-pass split, fp32 acc; layer 3 in registers.
__global__ void __launch_bounds__(128, 5)
k_edges(const float* __restrict__ cgm, const float* __restrict__ W1,
        const float* __restrict__ b2,  const float* __restrict__ W3,
        const float* __restrict__ b3,  int step, float sf) {
    __shared__ __align__(32) unsigned char pool[31792];
    // [0,4608) s_bhT ; [4608,9216) s_blT ; [9216,17408) s_bt2 ;
    // [17408,29696) s_a (4 warps x hi1536+lo1536) ; [29696,30720) s_rv ;
    // [30720,31232) s_wq ; [31232,31488) s_bw ; [31488,31616) s_f0j ;
    // [31616] f0i[4] ; [31632] pi[4] ; [31648] cand[32] ; [31776] b3 ; [31780] alive
    __nv_bfloat16* s_bhT = (__nv_bfloat16*)(pool);
    __nv_bfloat16* s_blT = (__nv_bfloat16*)(pool + 4608);
    float* s_bt2 = (float*)(pool + 9216);
    __nv_bfloat16* s_a = (__nv_bfloat16*)(pool + 17408);
    float* s_rv = (float*)(pool + 29696);
    float* s_wq = (float*)(pool + 30720);
    float2* s_bw = (float2*)(pool + 31232);
    float* s_f0j = (float*)(pool + 31488);
    float* s_f0i = (float*)(pool + 31616);
    float* s_pi  = (float*)(pool + 31632);
    unsigned* s_cand = (unsigned*)(pool + 31648);
    float* s_b3p = (float*)(pool + 31776);
    int* s_alive = (int*)(pool + 31780);

    int tid = threadIdx.x;
    int warp = tid >> 5, lane = tid & 31;
    int j0 = blockIdx.x * 32;
    int i0 = blockIdx.y * 4;

    if (tid == 0) *s_alive = 0;
    __syncthreads();
    if (tid < 4) {
        float p = g_p0[i0 + tid];                  // replay: p_s = max(p0, cand_0..s-1)
        for (int s = 0; s < step; s++)
            p = fmaxf(p, __uint_as_float(g_cand[s][i0 + tid]));
        s_pi[tid] = p;
        s_f0i[tid] = g_f0[i0 + tid];
        if (p > 0.f) atomicExch(s_alive, 1);
    }
    __syncthreads();
    if (!*s_alive) return;                         // all 4 rows dead (block-uniform)

    {   // prologue — vectorized
        const uint4* w2h4 = (const uint4*)g_w2hiT; // 288 uint4 each
        const uint4* w2l4 = (const uint4*)g_w2loT;
        uint4* sb0 = (uint4*)s_bhT;
        uint4* sb1 = (uint4*)s_blT;
        for (int idx = tid; idx < 288; idx += 128) {
            sb0[idx] = w2h4[idx];
            sb1[idx] = w2l4[idx];
        }
        const float4* bt4 = (const float4*)&g_Bt2[blockIdx.x][0]; // 512 float4
        float4* sbt4 = (float4*)s_bt2;
#pragma unroll
        for (int q = 0; q < 4; q++) sbt4[tid + 128 * q] = bt4[tid + 128 * q];
        for (int idx = tid; idx < 4 * D; idx += 128) {
            int r = idx >> 6, k = idx & 63;
            s_rv[idx] = fmaf(s_pi[r], W1[129 * D + k],
                        fmaf(sf, W1[130 * D + k], g_rowconst[(i0 + r) * D + k]));
        }
        s_wq[tid] = W1[(128 + 3 * (tid & 1)) * D + (tid >> 1)];
        if (tid < 32) { s_bw[tid] = make_float2(b2[tid], W3[tid]);
                        s_f0j[tid] = g_f0[j0 + tid]; s_cand[tid] = 0u; }
        if (tid == 0) *s_b3p = b3[0];
    }
    __syncthreads();

    float p_i = s_pi[warp];                        // warp-uniform guard
    if (p_i > 0.f) {
        float cg = cgm[(i0 + warp) * N + j0 + lane];
        float fd = fabsf(s_f0i[warp] - s_f0j[lane]);

        __nv_bfloat16* a_hi = s_a + warp * 1536;   // 32 rows x A_LDM; lo at +768 elems
        const float2* rv2 = (const float2*)(s_rv + warp * D);
        const float2* bt2 = (const float2*)s_bt2;
        const float4* wq4 = (const float4*)s_wq;

        // ldmatrix addresses (PTX-documented fragment quadrant order)
        int midx = lane >> 3, r8 = lane & 7;
        unsigned aAbase = smem_u32(a_hi);
        unsigned aoff = (unsigned)(((midx & 1) * 8 + r8) * 48 + (midx >> 1) * 16);
        unsigned aA0 = aAbase + aoff;              // mt=0
        unsigned aA1 = aA0 + 16 * 48;              // mt=1
        unsigned boff = (unsigned)((((midx >> 1) * 8 + r8) * 144) + (midx & 1) * 16);
        unsigned aBh = smem_u32(s_bhT) + boff;     // ntile pair 0; pair1 at +16*144
        unsigned aBl = smem_u32(s_blT) + boff;

        float acc[2][4][4];                        // [mt][nt][reg]
#pragma unroll
        for (int mt = 0; mt < 2; mt++)
#pragma unroll
            for (int nt = 0; nt < 4; nt++)
#pragma unroll
                for (int r = 0; r < 4; r++) acc[mt][nt][r] = 0.f;

#pragma unroll
        for (int ks = 0; ks < 4; ks++) {
            // ---- layer 1 for this 16-k chunk + exact bf16 split ----
            unsigned ahi[4], alo[4];
#pragma unroll
            for (int q = 0; q < 8; q++) {
                int k2 = ks * 8 + q;
                float4 wq = wq4[k2];
                float2 rv = rv2[k2];
                float2 bt = bt2[(k2 << 5) + lane];
                float h0 = fmaxf(fmaf(cg, wq.x, fmaf(fd, wq.y, rv.x + bt.x)), 0.f);
                float h1 = fmaxf(fmaf(cg, wq.z, fmaf(fd, wq.w, rv.y + bt.y)), 0.f);
                unsigned hb;
                asm("cvt.rn.bf16x2.f32 %0, %1, %2;" : "=r"(hb) : "f"(h1), "f"(h0));
                float f_lo = __uint_as_float(hb << 16);
                float f_hi = __uint_as_float(hb & 0xFFFF0000u);
                float r0 = h0 - f_lo, r1 = h1 - f_hi;
                unsigned lb;
                asm("cvt.rn.bf16x2.f32 %0, %1, %2;" : "=r"(lb) : "f"(r1), "f"(r0));
                ahi[q & 3] = hb; alo[q & 3] = lb;
                if ((q & 3) == 3) {                // flush 8 k's = 16 B per buffer
                    int half = q >> 2;
                    *(uint4*)((char*)a_hi + lane * 48 + half * 16) =
                        make_uint4(ahi[0], ahi[1], ahi[2], ahi[3]);
                    *(uint4*)((char*)a_hi + 1536 + lane * 48 + half * 16) =
                        make_uint4(alo[0], alo[1], alo[2], alo[3]);
                }
            }
            __syncwarp();

            // ---- fragments ----
            unsigned fa_hi[2][4], fa_lo[2][4], fb_hi[2][4], fb_lo[2][4];
            ldm_x4(fa_hi[0][0], fa_hi[0][1], fa_hi[0][2], fa_hi[0][3], aA0);
            ldm_x4(fa_hi[1][0], fa_hi[1][1], fa_hi[1][2], fa_hi[1][3], aA1);
            ldm_x4(fa_lo[0][0], fa_lo[0][1], fa_lo[0][2], fa_lo[0][3], aA0 + 1536);
            ldm_x4(fa_lo[1][0], fa_lo[1][1], fa_lo[1][2], fa_lo[1][3], aA1 + 1536);
            unsigned kb = (unsigned)(ks * 32);     // 16 k elems = 32 B
            ldm_x4(fb_hi[0][0], fb_hi[0][1], fb_hi[0][2], fb_hi[0][3], aBh + kb);
            ldm_x4(fb_hi[1][0], fb_hi[1][1], fb_hi[1][2], fb_hi[1][3], aBh + kb + 16 * 144);
            ldm_x4(fb_lo[0][0], fb_lo[0][1], fb_lo[0][2], fb_lo[0][3], aBl + kb);
            ldm_x4(fb_lo[1][0], fb_lo[1][1], fb_lo[1][2], fb_lo[1][3], aBl + kb + 16 * 144);

            // ---- 3-pass mma: hi.hi + lo.hi + hi.lo ----
#pragma unroll
            for (int mt = 0; mt < 2; mt++)
#pragma unroll
                for (int nt = 0; nt < 4; nt++) {
                    unsigned bh0 = fb_hi[nt >> 1][(nt & 1) * 2];
                    unsigned bh1 = fb_hi[nt >> 1][(nt & 1) * 2 + 1];
                    unsigned bl0 = fb_lo[nt >> 1][(nt & 1) * 2];
                    unsigned bl1 = fb_lo[nt >> 1][(nt & 1) * 2 + 1];
                    mma_bf16(acc[mt][nt], fa_hi[mt], bh0, bh1);
                    mma_bf16(acc[mt][nt], fa_lo[mt], bh0, bh1);
                    mma_bf16(acc[mt][nt], fa_hi[mt], bl0, bl1);
                }
            __syncwarp();                          // A buffer reuse next chunk
        }

        // ---- register epilogue (documented C fragment layout) ----
        // thread holds D rows {mt*16+g, +8}, cols {nt*8+2c, +1}; g=lane/4, c=lane&3
        int c2 = (lane & 3) * 2;
        float zp[2][2] = {{0.f, 0.f}, {0.f, 0.f}}; // [mt][rowhalf]
#pragma unroll
        for (int nt = 0; nt < 4; nt++) {
            float2 bw0 = s_bw[nt * 8 + c2];
            float2 bw1 = s_bw[nt * 8 + c2 + 1];
#pragma unroll
            for (int mt = 0; mt < 2; mt++) {
                zp[mt][0] = fmaf(fmaxf(acc[mt][nt][0] + bw0.x, 0.f), bw0.y, zp[mt][0]);
                zp[mt][0] = fmaf(fmaxf(acc[mt][nt][1] + bw1.x, 0.f), bw1.y, zp[mt][0]);
                zp[mt][1] = fmaf(fmaxf(acc[mt][nt][2] + bw0.x, 0.f), bw0.y, zp[mt][1]);
                zp[mt][1] = fmaf(fmaxf(acc[mt][nt][3] + bw1.x, 0.f), bw1.y, zp[mt][1]);
            }
        }
#pragma unroll
        for (int mt = 0; mt < 2; mt++)
#pragma unroll
            for (int h = 0; h < 2; h++) {
                zp[mt][h] += __shfl_xor_sync(0xFFFFFFFFu, zp[mt][h], 1);
                zp[mt][h] += __shfl_xor_sync(0xFFFFFFFFu, zp[mt][h], 2);
            }
        // route z[row] to lane=row: row = mt*16 + h*8 + g lives in lanes 4g..4g+3
        int src = (lane & 7) * 4;
        float s00 = __shfl_sync(0xFFFFFFFFu, zp[0][0], src);
        float s01 = __shfl_sync(0xFFFFFFFFu, zp[0][1], src);
        float s10 = __shfl_sync(0xFFFFFFFFu, zp[1][0], src);
        float s11 = __shfl_sync(0xFFFFFFFFu, zp[1][1], src);
        float zj = (lane < 16) ? ((lane & 8) ? s01 : s00)
                               : ((lane & 8) ? s11 : s10);
        float z = zj + *s_b3p;
        float tr = 1.f / (1.f + __expf(-z));
        float val = (cg > 0.f) ? p_i * tr * cg : 0.f;
        if (val > 0.f) atomicMax(&s_cand[lane], __float_as_uint(val)); // uint==float order, >=0
    }
    __syncthreads();
    if (tid < 32) {
        unsigned v = s_cand[tid];
        if (v) atomicMax(&g_cand[step][j0 + tid], v);
    }
}

// replay the 10-step max/arr recurrence exactly; write output
__global__ void k_final(float* __restrict__ out) {
    int j = threadIdx.x;                            // 512 threads
    float p = g_p0[j];
    float arr = (p > 0.f) ? 0.f : CUDART_INF_F;
#pragma unroll
    for (int s = 0; s < MAX_STEPS; s++) {
        float c = __uint_as_float(g_cand[s][j]);
        if (c > p) { p = c; arr = fminf(arr, (float)(s + 1)); }
    }
    out[j] = p; out[N + j] = arr;
}

// ---------------------------------------------------------------------------
extern "C" void kernel_launch(void* const* d_in, const int* in_sizes, int n_in,
                              void* d_out, int out_size) {
    const float* cg    = (const float*)d_in[0];
    const float* nf    = (const float*)d_in[1];
    const int*   shock = (const int*)  d_in[2];
    const float* W1    = (const float*)d_in[3];
    const float* b1    = (const float*)d_in[4];
    const float* W2    = (const float*)d_in[5];
    const float* b2    = (const float*)d_in[6];
    const float* W3    = (const float*)d_in[7];
    const float* b3    = (const float*)d_in[8];
    float* out = (float*)d_out;

    k_init_state<<<1, 512>>>(shock, in_sizes[2]);
    k_init_ab<<<128, 256>>>(nf, W1, b1, W2);
    for (int s = 0; s < MAX_STEPS; s++)
        k_edges<<<dim3(16, 128), 128>>>(cg, W1, b2, W3, b3,
                                        s, (float)s / (float)MAX_STEPS);
    k_final<<<1, 512>>>(out);
}

// round 16
// speedup vs baseline: 1.9978x; 1.0908x over previous
#include <cuda_runtime.h>
#include <cuda_bf16.h>
#include <math_constants.h>

#define N 512
#define D 64
#define MAX_STEPS 10
#define BT_LDM 72         // bf16 per W2^T row (144 B; ldmatrix conflict-free, pad unread)

// ---- persistent scratch ----
__device__ float         g_p0[N];
__device__ unsigned int  g_cand[MAX_STEPS][N];  // per-step candidate maxima (float bits)
__device__ float         g_rowconst[N * D];     // nf[i]@W1[0:64] + b1
// Bt per j-tile, XOR-swizzled fragment layout:
// float2 slot [k2][ j ^ ((k2&3)<<3) ] = (bt[2k2][j], bt[2k2+1][j])
__device__ __align__(16) float g_Bt2[16][D * 32];
__device__ float         g_f0[N];
__device__ __align__(16) __nv_bfloat16 g_w2hiT[32 * BT_LDM]; // [m][k] transposed, padded
__device__ __align__(16) __nv_bfloat16 g_w2loT[32 * BT_LDM]; // exact residual, transposed

// ---- mma / ldmatrix helpers ----
__device__ __forceinline__ unsigned smem_u32(const void* p) {
    return (unsigned)__cvta_generic_to_shared(p);
}
__device__ __forceinline__ void ldm_x4(unsigned& r0, unsigned& r1, unsigned& r2, unsigned& r3,
                                       unsigned addr) {
    asm volatile("ldmatrix.sync.aligned.m8n8.x4.shared.b16 {%0,%1,%2,%3}, [%4];"
                 : "=r"(r0), "=r"(r1), "=r"(r2), "=r"(r3) : "r"(addr));
}
__device__ __forceinline__ void mma_bf16(float* d, const unsigned* a, unsigned b0, unsigned b1) {
    asm volatile("mma.sync.aligned.m16n8k16.row.col.f32.bf16.bf16.f32 "
                 "{%0,%1,%2,%3}, {%4,%5,%6,%7}, {%8,%9}, {%0,%1,%2,%3};"
                 : "+f"(d[0]), "+f"(d[1]), "+f"(d[2]), "+f"(d[3])
                 : "r"(a[0]), "r"(a[1]), "r"(a[2]), "r"(a[3]), "r"(b0), "r"(b1));
}

// ---------------------------------------------------------------------------
__global__ void k_init_state(const int* __restrict__ shock, int n_shock) {
    int t = threadIdx.x;                    // 512 threads
    if (t < N) g_p0[t] = 0.f;
    unsigned int* c = &g_cand[0][0];
    for (int idx = t; idx < MAX_STEPS * N; idx += 512) c[idx] = 0u;
    __syncthreads();
    if (t < n_shock) g_p0[shock[t]] = 1.f;
}

__global__ void k_init_ab(const float* __restrict__ nf,
                          const float* __restrict__ W1,
                          const float* __restrict__ b1,
                          const float* __restrict__ W2) {
    int gid = blockIdx.x * 256 + threadIdx.x;      // < 32768
    int i = gid >> 6, k = gid & 63;
    float accA = b1[k];
#pragma unroll 8
    for (int d = 0; d < D; d++) accA = fmaf(nf[i * D + d], W1[d * D + k], accA);
    g_rowconst[gid] = accA;

    int j = gid & (N - 1), kk = gid >> 9;          // kk < 64
    float accB = 0.f;
#pragma unroll 8
    for (int d = 0; d < D; d++) accB = fmaf(nf[j * D + d], W1[(D + d) * D + kk], accB);
    {   // XOR-swizzled fragment layout
        int jl = j & 31, k2 = kk >> 1, par = kk & 1;
        int j2 = jl ^ ((k2 & 3) << 3);
        g_Bt2[j >> 5][(k2 * 32 + j2) * 2 + par] = accB;
    }

    if (gid < N) g_f0[gid] = nf[gid * D];
    if (gid < D * 32) {                            // W2 split, transposed to [m][k]
        int kw = gid >> 5, m = gid & 31;
        float w = W2[gid];                         // W2 row-major [k][m]
        __nv_bfloat16 h = __float2bfloat16(w);
        g_w2hiT[m * BT_LDM + kw] = h;
        g_w2loT[m * BT_LDM + kw] = __float2bfloat16(w - __bfloat162float(h));
    }
}

// ---------------------------------------------------------------------------
// Step kernel: 128 threads = 4 warps; warp w owns edge row i0+w across 32 j.
// A fragments for mma.sync m16n8k16 built DIRECTLY in registers: each thread
// computes the 16 h1 values its fragments need (no STS/ldmatrix round-trip).
__global__ void __launch_bounds__(128, 5)
k_edges(const float* __restrict__ cgm, const float* __restrict__ W1,
        const float* __restrict__ b2,  const float* __restrict__ W3,
        const float* __restrict__ b3,  int step, float sf) {
    __shared__ __align__(32) unsigned char pool[19520];
    // [0,4608) s_bhT ; [4608,9216) s_blT ; [9216,17408) s_bt2 ;
    // [17408,18432) s_rv ; [18432,18944) s_wq ; [18944,19200) s_bw ;
    // [19200,19328) s_f0j ; [19328] f0i[4] ; [19344] pi[4] ;
    // [19360] cand[32] ; [19488] b3 ; [19492] alive
    __nv_bfloat16* s_bhT = (__nv_bfloat16*)(pool);
    __nv_bfloat16* s_blT = (__nv_bfloat16*)(pool + 4608);
    float* s_bt2 = (float*)(pool + 9216);
    float* s_rv = (float*)(pool + 17408);
    float* s_wq = (float*)(pool + 18432);
    float2* s_bw = (float2*)(pool + 18944);
    float* s_f0j = (float*)(pool + 19200);
    float* s_f0i = (float*)(pool + 19328);
    float* s_pi  = (float*)(pool + 19344);
    unsigned* s_cand = (unsigned*)(pool + 19360);
    float* s_b3p = (float*)(pool + 19488);
    int* s_alive = (int*)(pool + 19492);

    int tid = threadIdx.x;
    int warp = tid >> 5, lane = tid & 31;
    int j0 = blockIdx.x * 32;
    int i0 = blockIdx.y * 4;

    if (tid == 0) *s_alive = 0;
    __syncthreads();
    if (tid < 4) {
        float p = g_p0[i0 + tid];                  // replay: p_s = max(p0, cand_0..s-1)
        for (int s = 0; s < step; s++)
            p = fmaxf(p, __uint_as_float(g_cand[s][i0 + tid]));
        s_pi[tid] = p;
        s_f0i[tid] = g_f0[i0 + tid];
        if (p > 0.f) atomicExch(s_alive, 1);
    }
    __syncthreads();
    if (!*s_alive) return;                         // all 4 rows dead (block-uniform)

    {   // prologue — vectorized
        const uint4* w2h4 = (const uint4*)g_w2hiT; // 288 uint4 each
        const uint4* w2l4 = (const uint4*)g_w2loT;
        uint4* sb0 = (uint4*)s_bhT;
        uint4* sb1 = (uint4*)s_blT;
        for (int idx = tid; idx < 288; idx += 128) {
            sb0[idx] = w2h4[idx];
            sb1[idx] = w2l4[idx];
        }
        const float4* bt4 = (const float4*)&g_Bt2[blockIdx.x][0]; // 512 float4
        float4* sbt4 = (float4*)s_bt2;
#pragma unroll
        for (int q = 0; q < 4; q++) sbt4[tid + 128 * q] = bt4[tid + 128 * q];
        for (int idx = tid; idx < 4 * D; idx += 128) {
            int r = idx >> 6, k = idx & 63;
            s_rv[idx] = fmaf(s_pi[r], W1[129 * D + k],
                        fmaf(sf, W1[130 * D + k], g_rowconst[(i0 + r) * D + k]));
        }
        s_wq[tid] = W1[(128 + 3 * (tid & 1)) * D + (tid >> 1)];
        if (tid < 32) { s_bw[tid] = make_float2(b2[tid], W3[tid]);
                        s_f0j[tid] = g_f0[j0 + tid]; s_cand[tid] = 0u; }
        if (tid == 0) *s_b3p = b3[0];
    }
    __syncthreads();

    float p_i = s_pi[warp];                        // warp-uniform guard
    if (p_i > 0.f) {
        float cg = cgm[(i0 + warp) * N + j0 + lane];
        float fd = fabsf(s_f0i[warp] - s_f0j[lane]);

        int g = lane >> 2, c = lane & 3;
        // redistribute cg/fd to this thread's fragment rows j = 16mt+8h+g
        float cg_r[2][2], fd_r[2][2];
#pragma unroll
        for (int mt = 0; mt < 2; mt++)
#pragma unroll
            for (int h = 0; h < 2; h++) {
                int src = 16 * mt + 8 * h + g;
                cg_r[mt][h] = __shfl_sync(0xFFFFFFFFu, cg, src);
                fd_r[mt][h] = __shfl_sync(0xFFFFFFFFu, fd, src);
            }

        const float2* rv2 = (const float2*)(s_rv + warp * D);
        const float4* wq4 = (const float4*)s_wq;
        const float2* bt2f = (const float2*)s_bt2;

        // B ldmatrix addressing (unchanged, validated)
        int midx = lane >> 3, r8 = lane & 7;
        unsigned boff = (unsigned)((((midx >> 1) * 8 + r8) * 144) + (midx & 1) * 16);
        unsigned aBh = smem_u32(s_bhT) + boff;     // ntile pair 0; pair1 at +16*144
        unsigned aBl = smem_u32(s_blT) + boff;

        float acc[2][4][4];                        // [mt][nt][reg]
#pragma unroll
        for (int mt = 0; mt < 2; mt++)
#pragma unroll
            for (int nt = 0; nt < 4; nt++)
#pragma unroll
                for (int r = 0; r < 4; r++) acc[mt][nt][r] = 0.f;

#pragma unroll
        for (int ks = 0; ks < 4; ks++) {
            int k2a = 8 * ks + c, k2b = k2a + 4;   // both have (k2&3)==c
            float2 rvA = rv2[k2a], rvB = rv2[k2b];
            float4 wqA = wq4[k2a], wqB = wq4[k2b];

            unsigned fa_hi[2][4], fa_lo[2][4];
#pragma unroll
            for (int mt = 0; mt < 2; mt++)
#pragma unroll
                for (int h = 0; h < 2; h++) {
                    int jj = 16 * mt + 8 * h + g;
                    int jA = jj ^ (c << 3);        // bake-time swizzle
                    float2 btA = bt2f[k2a * 32 + jA];
                    float2 btB = bt2f[k2b * 32 + jA];
                    float cgv = cg_r[mt][h], fdv = fd_r[mt][h];
                    // k-pair A (k = 16ks+2c, +1)
                    float hA0 = fmaxf(fmaf(cgv, wqA.x, fmaf(fdv, wqA.y, rvA.x + btA.x)), 0.f);
                    float hA1 = fmaxf(fmaf(cgv, wqA.z, fmaf(fdv, wqA.w, rvA.y + btA.y)), 0.f);
                    unsigned hb;
                    asm("cvt.rn.bf16x2.f32 %0, %1, %2;" : "=r"(hb) : "f"(hA1), "f"(hA0));
                    float fl = __uint_as_float(hb << 16);
                    float fh = __uint_as_float(hb & 0xFFFF0000u);
                    unsigned lb;
                    asm("cvt.rn.bf16x2.f32 %0, %1, %2;" : "=r"(lb)
                        : "f"(hA1 - fh), "f"(hA0 - fl));
                    fa_hi[mt][h] = hb; fa_lo[mt][h] = lb;
                    // k-pair B (k = 16ks+8+2c, +1)
                    float hB0 = fmaxf(fmaf(cgv, wqB.x, fmaf(fdv, wqB.y, rvB.x + btB.x)), 0.f);
                    float hB1 = fmaxf(fmaf(cgv, wqB.z, fmaf(fdv, wqB.w, rvB.y + btB.y)), 0.f);
                    unsigned hb2;
                    asm("cvt.rn.bf16x2.f32 %0, %1, %2;" : "=r"(hb2) : "f"(hB1), "f"(hB0));
                    float fl2 = __uint_as_float(hb2 << 16);
                    float fh2 = __uint_as_float(hb2 & 0xFFFF0000u);
                    unsigned lb2;
                    asm("cvt.rn.bf16x2.f32 %0, %1, %2;" : "=r"(lb2)
                        : "f"(hB1 - fh2), "f"(hB0 - fl2));
                    fa_hi[mt][2 + h] = hb2; fa_lo[mt][2 + h] = lb2;
                }

            // ---- B fragments (unchanged) ----
            unsigned fb_hi[2][4], fb_lo[2][4];
            unsigned kb = (unsigned)(ks * 32);     // 16 k elems = 32 B
            ldm_x4(fb_hi[0][0], fb_hi[0][1], fb_hi[0][2], fb_hi[0][3], aBh + kb);
            ldm_x4(fb_hi[1][0], fb_hi[1][1], fb_hi[1][2], fb_hi[1][3], aBh + kb + 16 * 144);
            ldm_x4(fb_lo[0][0], fb_lo[0][1], fb_lo[0][2], fb_lo[0][3], aBl + kb);
            ldm_x4(fb_lo[1][0], fb_lo[1][1], fb_lo[1][2], fb_lo[1][3], aBl + kb + 16 * 144);

            // ---- 3-pass mma: hi.hi + lo.hi + hi.lo (unchanged) ----
#pragma unroll
            for (int mt = 0; mt < 2; mt++)
#pragma unroll
                for (int nt = 0; nt < 4; nt++) {
                    unsigned bh0 = fb_hi[nt >> 1][(nt & 1) * 2];
                    unsigned bh1 = fb_hi[nt >> 1][(nt & 1) * 2 + 1];
                    unsigned bl0 = fb_lo[nt >> 1][(nt & 1) * 2];
                    unsigned bl1 = fb_lo[nt >> 1][(nt & 1) * 2 + 1];
                    mma_bf16(acc[mt][nt], fa_hi[mt], bh0, bh1);
                    mma_bf16(acc[mt][nt], fa_lo[mt], bh0, bh1);
                    mma_bf16(acc[mt][nt], fa_hi[mt], bl0, bl1);
                }
        }

        // ---- register epilogue (unchanged, validated) ----
        int c2 = (lane & 3) * 2;
        float zp[2][2] = {{0.f, 0.f}, {0.f, 0.f}}; // [mt][rowhalf]
#pragma unroll
        for (int nt = 0; nt < 4; nt++) {
            float2 bw0 = s_bw[nt * 8 + c2];
            float2 bw1 = s_bw[nt * 8 + c2 + 1];
#pragma unroll
            for (int mt = 0; mt < 2; mt++) {
                zp[mt][0] = fmaf(fmaxf(acc[mt][nt][0] + bw0.x, 0.f), bw0.y, zp[mt][0]);
                zp[mt][0] = fmaf(fmaxf(acc[mt][nt][1] + bw1.x, 0.f), bw1.y, zp[mt][0]);
                zp[mt][1] = fmaf(fmaxf(acc[mt][nt][2] + bw0.x, 0.f), bw0.y, zp[mt][1]);
                zp[mt][1] = fmaf(fmaxf(acc[mt][nt][3] + bw1.x, 0.f), bw1.y, zp[mt][1]);
            }
        }
#pragma unroll
        for (int mt = 0; mt < 2; mt++)
#pragma unroll
            for (int h = 0; h < 2; h++) {
                zp[mt][h] += __shfl_xor_sync(0xFFFFFFFFu, zp[mt][h], 1);
                zp[mt][h] += __shfl_xor_sync(0xFFFFFFFFu, zp[mt][h], 2);
            }
        int src = (lane & 7) * 4;
        float s00 = __shfl_sync(0xFFFFFFFFu, zp[0][0], src);
        float s01 = __shfl_sync(0xFFFFFFFFu, zp[0][1], src);
        float s10 = __shfl_sync(0xFFFFFFFFu, zp[1][0], src);
        float s11 = __shfl_sync(0xFFFFFFFFu, zp[1][1], src);
        float zj = (lane < 16) ? ((lane & 8) ? s01 : s00)
                               : ((lane & 8) ? s11 : s10);
        float z = zj + *s_b3p;
        float tr = 1.f / (1.f + __expf(-z));
        float val = (cg > 0.f) ? p_i * tr * cg : 0.f;
        if (val > 0.f) atomicMax(&s_cand[lane], __float_as_uint(val)); // uint==float order, >=0
    }
    __syncthreads();
    if (tid < 32) {
        unsigned v = s_cand[tid];
        if (v) atomicMax(&g_cand[step][j0 + tid], v);
    }
}

// replay the 10-step max/arr recurrence exactly; write output
__global__ void k_final(float* __restrict__ out) {
    int j = threadIdx.x;                            // 512 threads
    float p = g_p0[j];
    float arr = (p > 0.f) ? 0.f : CUDART_INF_F;
#pragma unroll
    for (int s = 0; s < MAX_STEPS; s++) {
        float c = __uint_as_float(g_cand[s][j]);
        if (c > p) { p = c; arr = fminf(arr, (float)(s + 1)); }
    }
    out[j] = p; out[N + j] = arr;
}

// ---------------------------------------------------------------------------
extern "C" void kernel_launch(void* const* d_in, const int* in_sizes, int n_in,
                              void* d_out, int out_size) {
    const float* cg    = (const float*)d_in[0];
    const float* nf    = (const float*)d_in[1];
    const int*   shock = (const int*)  d_in[2];
    const float* W1    = (const float*)d_in[3];
    const float* b1    = (const float*)d_in[4];
    const float* W2    = (const float*)d_in[5];
    const float* b2    = (const float*)d_in[6];
    const float* W3    = (const float*)d_in[7];
    const float* b3    = (const float*)d_in[8];
    float* out = (float*)d_out;

    k_init_state<<<1, 512>>>(shock, in_sizes[2]);
    k_init_ab<<<128, 256>>>(nf, W1, b1, W2);
    for (int s = 0; s < MAX_STEPS; s++)
        k_edges<<<dim3(16, 128), 128>>>(cg, W1, b2, W3, b3,
                                        s, (float)s / (float)MAX_STEPS);
    k_final<<<1, 512>>>(out);
}